// round 5
// baseline (speedup 1.0000x reference)
#include <cuda_runtime.h>
#include <math_constants.h>

// ---------------------------------------------------------------------------
// EwaldReciprocal: B=2, N=4096, NK=4096 — 2 launches, MUFU-saturating.
//   sf:    partials S_part[z][b][k]; last z-block per k-slice reduces the 32
//          partials, folds expfac -> g_es, and publishes g_kc4.
//   recip: 4 atoms/thread; staging = 2 vector loads per k; last z-block per
//          atom-slice finalizes phi and resets state (graph-replay safe).
// ---------------------------------------------------------------------------

#define NCH_SF 32
#define MAXK   8192
#define MAXBN  32768

__device__ float2 g_Spart[NCH_SF * 2 * MAXK];  // [z][b][k]
__device__ float4 g_kc4[MAXK];                 // 2*pi * kvec @ cell_inv
__device__ float2 g_es[2 * MAXK];              // expfac * (Sre, Sim) per [b][k]
__device__ float  g_recip[MAXBN];              // zero at entry; re-zeroed at end
__device__ int    g_cnt_sf[64];                // per (b,x) slice counters
__device__ int    g_cnt_rc[64];

// ---------------- kernel 1: structure factor + fused reduction --------------
// 2 k per thread; grid (NK/512, B, 32). Last z-block per slice reduces.
#define SF_BLK 256
__global__ void sf_kernel(const float* __restrict__ coords,
                          const float* __restrict__ q,
                          const float* __restrict__ kvec,
                          const float* __restrict__ cell_inv,
                          const float* __restrict__ expfac,
                          int N, int NK, int nchunk) {
    __shared__ float4 sh[SF_BLK];
    __shared__ int s_last;
    int b  = blockIdx.y;
    int z  = blockIdx.z;
    int kA = blockIdx.x * (SF_BLK * 2) + threadIdx.x;
    int kB = kA + SF_BLK;
    int n0 = z * nchunk;
    int n1 = min(n0 + nchunk, N);

    const float twopi = 6.283185307179586f;
    float ci[9];
    #pragma unroll
    for (int i = 0; i < 9; i++) ci[i] = __ldg(&cell_inv[i]);

    float4 kcA = make_float4(0.f, 0.f, 0.f, 0.f);
    float4 kcB = make_float4(0.f, 0.f, 0.f, 0.f);
    if (kA < NK) {
        float kx = kvec[kA * 3 + 0], ky = kvec[kA * 3 + 1], kz = kvec[kA * 3 + 2];
        kcA.x = twopi * (kx * ci[0] + ky * ci[3] + kz * ci[6]);
        kcA.y = twopi * (kx * ci[1] + ky * ci[4] + kz * ci[7]);
        kcA.z = twopi * (kx * ci[2] + ky * ci[5] + kz * ci[8]);
    }
    if (kB < NK) {
        float kx = kvec[kB * 3 + 0], ky = kvec[kB * 3 + 1], kz = kvec[kB * 3 + 2];
        kcB.x = twopi * (kx * ci[0] + ky * ci[3] + kz * ci[6]);
        kcB.y = twopi * (kx * ci[1] + ky * ci[4] + kz * ci[7]);
        kcB.z = twopi * (kx * ci[2] + ky * ci[5] + kz * ci[8]);
    }

    float sreA = 0.f, simA = 0.f, sreB = 0.f, simB = 0.f;

    for (int t = n0; t < n1; t += SF_BLK) {
        int nt = min(SF_BLK, n1 - t);
        if ((int)threadIdx.x < nt) {
            int n = t + threadIdx.x;
            const float* cp = coords + ((size_t)b * N + n) * 3;
            sh[threadIdx.x] = make_float4(cp[0], cp[1], cp[2], q[(size_t)b * N + n]);
        }
        __syncthreads();
        #pragma unroll 8
        for (int j = 0; j < nt; j++) {
            float4 a = sh[j];
            float thA = fmaf(kcA.x, a.x, fmaf(kcA.y, a.y, kcA.z * a.z));
            float thB = fmaf(kcB.x, a.x, fmaf(kcB.y, a.y, kcB.z * a.z));
            float sA, cA, sB, cB;
            __sincosf(thA, &sA, &cA);
            __sincosf(thB, &sB, &cB);
            sreA = fmaf(a.w, cA, sreA);
            simA = fmaf(a.w, sA, simA);
            sreB = fmaf(a.w, cB, sreB);
            simB = fmaf(a.w, sB, simB);
        }
        __syncthreads();
    }
    if (kA < NK) g_Spart[(z * 2 + b) * NK + kA] = make_float2(sreA, simA);
    if (kB < NK) g_Spart[(z * 2 + b) * NK + kB] = make_float2(sreB, simB);

    // ---- last z-block of this (b, k-range) slice reduces partials ----------
    __threadfence();
    int slice = b * gridDim.x + blockIdx.x;
    if (threadIdx.x == 0) {
        int c = atomicAdd(&g_cnt_sf[slice], 1);
        s_last = (c == (int)gridDim.z - 1) ? 1 : 0;
    }
    __syncthreads();
    if (s_last) {
        if (kA < NK) {
            float sre = 0.f, sim = 0.f;
            #pragma unroll
            for (int zz = 0; zz < NCH_SF; zz++) {
                float2 p = g_Spart[(zz * 2 + b) * NK + kA];
                sre += p.x; sim += p.y;
            }
            float e = expfac[kA];
            g_es[b * NK + kA] = make_float2(e * sre, e * sim);
            g_kc4[kA] = kcA;
        }
        if (kB < NK) {
            float sre = 0.f, sim = 0.f;
            #pragma unroll
            for (int zz = 0; zz < NCH_SF; zz++) {
                float2 p = g_Spart[(zz * 2 + b) * NK + kB];
                sre += p.x; sim += p.y;
            }
            float e = expfac[kB];
            g_es[b * NK + kB] = make_float2(e * sre, e * sim);
            g_kc4[kB] = kcB;
        }
        if (threadIdx.x == 0) g_cnt_sf[slice] = 0;
    }
}

// ---------------- kernel 2: recip + fused finalize ---------------------------
// 4 atoms per thread; grid (N/1024, B, 64). Staging = 2 vector loads per k.
#define RC_BLK 256
__global__ void recip_kernel(const float* __restrict__ coords,
                             const float* __restrict__ q,
                             const float* __restrict__ volume,
                             const float* __restrict__ bewald,
                             float* __restrict__ out,
                             int N, int NK, int kchunk, int BN) {
    __shared__ float4 skc[RC_BLK];
    __shared__ float2 ses[RC_BLK];
    __shared__ int s_last;
    int b    = blockIdx.y;
    int base = blockIdx.x * (RC_BLK * 4);
    int k0 = blockIdx.z * kchunk;
    int k1 = min(k0 + kchunk, NK);

    float x0 = 0.f, y0 = 0.f, z0 = 0.f, x1 = 0.f, y1 = 0.f, z1 = 0.f;
    float x2 = 0.f, y2 = 0.f, z2 = 0.f, x3 = 0.f, y3 = 0.f, z3 = 0.f;
    {
        int n;
        const float* cp;
        n = base + 0 * RC_BLK + threadIdx.x;
        if (n < N) { cp = coords + ((size_t)b * N + n) * 3; x0 = cp[0]; y0 = cp[1]; z0 = cp[2]; }
        n = base + 1 * RC_BLK + threadIdx.x;
        if (n < N) { cp = coords + ((size_t)b * N + n) * 3; x1 = cp[0]; y1 = cp[1]; z1 = cp[2]; }
        n = base + 2 * RC_BLK + threadIdx.x;
        if (n < N) { cp = coords + ((size_t)b * N + n) * 3; x2 = cp[0]; y2 = cp[1]; z2 = cp[2]; }
        n = base + 3 * RC_BLK + threadIdx.x;
        if (n < N) { cp = coords + ((size_t)b * N + n) * 3; x3 = cp[0]; y3 = cp[1]; z3 = cp[2]; }
    }
    float acc0 = 0.f, acc1 = 0.f, acc2 = 0.f, acc3 = 0.f;

    for (int t = k0; t < k1; t += RC_BLK) {
        int nt = min(RC_BLK, k1 - t);
        if ((int)threadIdx.x < nt) {
            int k = t + threadIdx.x;
            skc[threadIdx.x] = g_kc4[k];
            ses[threadIdx.x] = g_es[b * NK + k];
        }
        __syncthreads();
        #pragma unroll 8
        for (int j = 0; j < nt; j++) {
            float4 kc = skc[j];
            float2 es = ses[j];
            float th0 = fmaf(kc.x, x0, fmaf(kc.y, y0, kc.z * z0));
            float th1 = fmaf(kc.x, x1, fmaf(kc.y, y1, kc.z * z1));
            float th2 = fmaf(kc.x, x2, fmaf(kc.y, y2, kc.z * z2));
            float th3 = fmaf(kc.x, x3, fmaf(kc.y, y3, kc.z * z3));
            float s0, c0, s1, c1, s2, c2, s3, c3;
            __sincosf(th0, &s0, &c0);
            __sincosf(th1, &s1, &c1);
            __sincosf(th2, &s2, &c2);
            __sincosf(th3, &s3, &c3);
            acc0 = fmaf(es.x, c0, fmaf(es.y, s0, acc0));
            acc1 = fmaf(es.x, c1, fmaf(es.y, s1, acc1));
            acc2 = fmaf(es.x, c2, fmaf(es.y, s2, acc2));
            acc3 = fmaf(es.x, c3, fmaf(es.y, s3, acc3));
        }
        __syncthreads();
    }
    {
        int n;
        n = base + 0 * RC_BLK + threadIdx.x; if (n < N) atomicAdd(&g_recip[b * N + n], acc0);
        n = base + 1 * RC_BLK + threadIdx.x; if (n < N) atomicAdd(&g_recip[b * N + n], acc1);
        n = base + 2 * RC_BLK + threadIdx.x; if (n < N) atomicAdd(&g_recip[b * N + n], acc2);
        n = base + 3 * RC_BLK + threadIdx.x; if (n < N) atomicAdd(&g_recip[b * N + n], acc3);
    }

    // ---- last z-block of this atom-slice finalizes & resets ----------------
    __threadfence();
    int slice = b * gridDim.x + blockIdx.x;
    if (threadIdx.x == 0) {
        int c = atomicAdd(&g_cnt_rc[slice], 1);
        s_last = (c == (int)gridDim.z - 1) ? 1 : 0;
    }
    __syncthreads();
    if (s_last) {
        const float BOHR = 1.8897261258369282f;
        const float INV_SQRT_PI = 0.5641895835477563f;
        float scale = BOHR / (CUDART_PI_F * volume[0]);
        float selfc = 2.0f * bewald[0] * BOHR * INV_SQRT_PI;
        #pragma unroll
        for (int a = 0; a < 4; a++) {
            int n = base + a * RC_BLK + threadIdx.x;
            if (n < N) {
                int i = b * N + n;
                float r = g_recip[i];
                g_recip[i] = 0.0f;                 // reset for next replay
                float qi = q[i];
                float phi = r * scale - qi * selfc;
                out[i] = 0.5f * qi * phi;
                out[BN + i] = phi;
            }
        }
        if (threadIdx.x == 0) g_cnt_rc[slice] = 0;
    }
}

// ---------------------------------------------------------------------------
extern "C" void kernel_launch(void* const* d_in, const int* in_sizes, int n_in,
                              void* d_out, int out_size) {
    const float* coords   = (const float*)d_in[0];
    const float* q        = (const float*)d_in[1];
    const float* cell_inv = (const float*)d_in[2];
    const float* kvec     = (const float*)d_in[3];
    const float* expfac   = (const float*)d_in[4];
    const float* volume   = (const float*)d_in[5];
    const float* bewald   = (const float*)d_in[6];
    float* out = (float*)d_out;

    int BN = in_sizes[1];       // B*N
    int NK = in_sizes[4];
    int B  = 2;                 // fixed shape for this problem
    int N  = BN / B;

    // sf: 512 k / block, 32 atom-chunks -> 8*2*32 = 512 blocks (single wave)
    {
        int nchunk = (N + NCH_SF - 1) / NCH_SF;
        dim3 grid((NK + SF_BLK * 2 - 1) / (SF_BLK * 2), B, NCH_SF);
        sf_kernel<<<grid, SF_BLK>>>(coords, q, kvec, cell_inv, expfac,
                                    N, NK, nchunk);
    }

    // recip: 1024 atoms / block, 64 k-chunks -> 4*2*64 = 512 blocks
    {
        int kchunks = 64;
        int kchunk = (NK + kchunks - 1) / kchunks;
        dim3 grid((N + RC_BLK * 4 - 1) / (RC_BLK * 4), B, kchunks);
        recip_kernel<<<grid, RC_BLK>>>(coords, q, volume, bewald, out,
                                       N, NK, kchunk, BN);
    }
}

// round 6
// speedup vs baseline: 1.0887x; 1.0887x over previous
#include <cuda_runtime.h>
#include <math_constants.h>

// ---------------------------------------------------------------------------
// EwaldReciprocal: B=2, N=4096, NK=4096 — 3 launches.
//   sf:     S_part[z][b][k] partials (R4-proven config, MUFU-saturated ~15us)
//   reduce: fold 32 partials + expfac -> g_t1=(kc,e*Sre), g_t2=(kc,e*Sim)
//   recip:  two sf-shaped passes (cos pass over g_t1, sin pass over g_t2);
//           last z-block per atom slice finalizes phi and resets state.
// ---------------------------------------------------------------------------

#define NCH_SF 32
#define MAXK   8192
#define MAXBN  32768

__device__ float2 g_Spart[NCH_SF * 2 * MAXK];  // [z][b][k]
__device__ float4 g_t1[2 * MAXK];              // (kc.x, kc.y, kc.z, e*Sre) [b][k]
__device__ float4 g_t2[2 * MAXK];              // (kc.x, kc.y, kc.z, e*Sim) [b][k]
__device__ float  g_recip[MAXBN];              // zero at entry; re-zeroed at end
__device__ int    g_cnt_rc[64];

// ---------------- kernel 1: structure factor partials (R4 exact) ------------
// 1 k per thread; grid (NK/256, B, 32). kc inline. No atomics, no zeroing.
#define SF_BLK 256
__global__ void sf_kernel(const float* __restrict__ coords,
                          const float* __restrict__ q,
                          const float* __restrict__ kvec,
                          const float* __restrict__ cell_inv,
                          int N, int NK, int nchunk) {
    __shared__ float4 sh[SF_BLK];
    int b = blockIdx.y;
    int z = blockIdx.z;
    int k = blockIdx.x * SF_BLK + threadIdx.x;
    int n0 = z * nchunk;
    int n1 = min(n0 + nchunk, N);

    const float twopi = 6.283185307179586f;
    float ci[9];
    #pragma unroll
    for (int i = 0; i < 9; i++) ci[i] = __ldg(&cell_inv[i]);

    float kcx = 0.f, kcy = 0.f, kcz = 0.f;
    if (k < NK) {
        float kx = kvec[k * 3 + 0], ky = kvec[k * 3 + 1], kz = kvec[k * 3 + 2];
        kcx = twopi * (kx * ci[0] + ky * ci[3] + kz * ci[6]);
        kcy = twopi * (kx * ci[1] + ky * ci[4] + kz * ci[7]);
        kcz = twopi * (kx * ci[2] + ky * ci[5] + kz * ci[8]);
    }

    float sre = 0.f, sim = 0.f;

    for (int t = n0; t < n1; t += SF_BLK) {
        int nt = min(SF_BLK, n1 - t);
        if ((int)threadIdx.x < nt) {
            int n = t + threadIdx.x;
            const float* cp = coords + ((size_t)b * N + n) * 3;
            sh[threadIdx.x] = make_float4(cp[0], cp[1], cp[2], q[(size_t)b * N + n]);
        }
        __syncthreads();
        #pragma unroll 4
        for (int j = 0; j < nt; j++) {
            float4 a = sh[j];
            float th = fmaf(kcx, a.x, fmaf(kcy, a.y, kcz * a.z));
            float s, c;
            __sincosf(th, &s, &c);
            sre = fmaf(a.w, c, sre);
            sim = fmaf(a.w, s, sim);
        }
        __syncthreads();
    }
    if (k < NK)
        g_Spart[(z * 2 + b) * NK + k] = make_float2(sre, sim);
}

// ---------------- kernel 2: reduce partials, pack recip tiles ----------------
__global__ void reduce_kernel(const float* __restrict__ kvec,
                              const float* __restrict__ cell_inv,
                              const float* __restrict__ expfac,
                              int NK, int BK) {
    int i = blockIdx.x * blockDim.x + threadIdx.x;
    if (i >= BK) return;
    int b = i / NK;
    int k = i - b * NK;

    float sre = 0.f, sim = 0.f;
    #pragma unroll
    for (int zz = 0; zz < NCH_SF; zz++) {
        float2 p = g_Spart[(zz * 2 + b) * NK + k];
        sre += p.x; sim += p.y;
    }
    const float twopi = 6.283185307179586f;
    float ci[9];
    #pragma unroll
    for (int j = 0; j < 9; j++) ci[j] = __ldg(&cell_inv[j]);
    float kx = kvec[k * 3 + 0], ky = kvec[k * 3 + 1], kz = kvec[k * 3 + 2];
    float kcx = twopi * (kx * ci[0] + ky * ci[3] + kz * ci[6]);
    float kcy = twopi * (kx * ci[1] + ky * ci[4] + kz * ci[7]);
    float kcz = twopi * (kx * ci[2] + ky * ci[5] + kz * ci[8]);
    float e = expfac[k];
    g_t1[i] = make_float4(kcx, kcy, kcz, e * sre);
    g_t2[i] = make_float4(kcx, kcy, kcz, e * sim);
}

// ---------------- kernel 3: recip (two sf-shaped passes) + finalize ----------
// 2 atoms per thread; grid (N/512, B, 64). Per k-tile: cos pass then sin pass.
#define RC_BLK 256
__global__ void recip_kernel(const float* __restrict__ coords,
                             const float* __restrict__ q,
                             const float* __restrict__ volume,
                             const float* __restrict__ bewald,
                             float* __restrict__ out,
                             int N, int NK, int kchunk, int BN) {
    __shared__ float4 st1[RC_BLK];
    __shared__ float4 st2[RC_BLK];
    __shared__ int s_last;
    int b  = blockIdx.y;
    int nA = blockIdx.x * (RC_BLK * 2) + threadIdx.x;
    int nB = nA + RC_BLK;
    int k0 = blockIdx.z * kchunk;
    int k1 = min(k0 + kchunk, NK);

    float xA = 0.f, yA = 0.f, zA = 0.f, xB = 0.f, yB = 0.f, zB = 0.f;
    if (nA < N) {
        const float* cp = coords + ((size_t)b * N + nA) * 3;
        xA = cp[0]; yA = cp[1]; zA = cp[2];
    }
    if (nB < N) {
        const float* cp = coords + ((size_t)b * N + nB) * 3;
        xB = cp[0]; yB = cp[1]; zB = cp[2];
    }
    float accA = 0.f, accB = 0.f;

    for (int t = k0; t < k1; t += RC_BLK) {
        int nt = min(RC_BLK, k1 - t);
        if ((int)threadIdx.x < nt) {
            int k = t + threadIdx.x;
            st1[threadIdx.x] = g_t1[b * NK + k];
            st2[threadIdx.x] = g_t2[b * NK + k];
        }
        __syncthreads();
        // --- cos pass (sf-shaped: 1 LDS.128, 1 MUFU per atom, FFMA) ---------
        #pragma unroll 4
        for (int j = 0; j < nt; j++) {
            float4 v = st1[j];
            float thA = fmaf(v.x, xA, fmaf(v.y, yA, v.z * zA));
            float thB = fmaf(v.x, xB, fmaf(v.y, yB, v.z * zB));
            accA = fmaf(v.w, __cosf(thA), accA);
            accB = fmaf(v.w, __cosf(thB), accB);
        }
        // --- sin pass --------------------------------------------------------
        #pragma unroll 4
        for (int j = 0; j < nt; j++) {
            float4 v = st2[j];
            float thA = fmaf(v.x, xA, fmaf(v.y, yA, v.z * zA));
            float thB = fmaf(v.x, xB, fmaf(v.y, yB, v.z * zB));
            accA = fmaf(v.w, __sinf(thA), accA);
            accB = fmaf(v.w, __sinf(thB), accB);
        }
        __syncthreads();
    }
    if (nA < N) atomicAdd(&g_recip[b * N + nA], accA);
    if (nB < N) atomicAdd(&g_recip[b * N + nB], accB);

    // ---- last z-block of this atom-slice finalizes & resets ----------------
    __threadfence();
    int slice = b * gridDim.x + blockIdx.x;
    if (threadIdx.x == 0) {
        int c = atomicAdd(&g_cnt_rc[slice], 1);
        s_last = (c == (int)gridDim.z - 1) ? 1 : 0;
    }
    __syncthreads();
    if (s_last) {
        const float BOHR = 1.8897261258369282f;
        const float INV_SQRT_PI = 0.5641895835477563f;
        float scale = BOHR / (CUDART_PI_F * volume[0]);
        float selfc = 2.0f * bewald[0] * BOHR * INV_SQRT_PI;
        int base = blockIdx.x * (RC_BLK * 2);
        #pragma unroll
        for (int a = 0; a < 2; a++) {
            int n = base + a * RC_BLK + threadIdx.x;
            if (n < N) {
                int i = b * N + n;
                float r = g_recip[i];
                g_recip[i] = 0.0f;                 // reset for next replay
                float qi = q[i];
                float phi = r * scale - qi * selfc;
                out[i] = 0.5f * qi * phi;
                out[BN + i] = phi;
            }
        }
        if (threadIdx.x == 0) g_cnt_rc[slice] = 0;
    }
}

// ---------------------------------------------------------------------------
extern "C" void kernel_launch(void* const* d_in, const int* in_sizes, int n_in,
                              void* d_out, int out_size) {
    const float* coords   = (const float*)d_in[0];
    const float* q        = (const float*)d_in[1];
    const float* cell_inv = (const float*)d_in[2];
    const float* kvec     = (const float*)d_in[3];
    const float* expfac   = (const float*)d_in[4];
    const float* volume   = (const float*)d_in[5];
    const float* bewald   = (const float*)d_in[6];
    float* out = (float*)d_out;

    int BN = in_sizes[1];       // B*N
    int NK = in_sizes[4];
    int B  = 2;                 // fixed shape for this problem
    int N  = BN / B;
    int BK = B * NK;

    // sf: 256 k / block, 32 atom-chunks -> 16*2*32 = 1024 blocks
    {
        int nchunk = (N + NCH_SF - 1) / NCH_SF;
        dim3 grid((NK + SF_BLK - 1) / SF_BLK, B, NCH_SF);
        sf_kernel<<<grid, SF_BLK>>>(coords, q, kvec, cell_inv, N, NK, nchunk);
    }

    // reduce: fold partials + expfac, pack tiles
    reduce_kernel<<<(BK + 255) / 256, 256>>>(kvec, cell_inv, expfac, NK, BK);

    // recip: 512 atoms / block, 64 k-chunks -> 8*2*64 = 1024 blocks
    {
        int kchunks = 64;
        int kchunk = (NK + kchunks - 1) / kchunks;
        dim3 grid((N + RC_BLK * 2 - 1) / (RC_BLK * 2), B, kchunks);
        recip_kernel<<<grid, RC_BLK>>>(coords, q, volume, bewald, out,
                                       N, NK, kchunk, BN);
    }
}

// round 7
// speedup vs baseline: 1.1463x; 1.0529x over previous
#include <cuda_runtime.h>
#include <math_constants.h>

// ---------------------------------------------------------------------------
// EwaldReciprocal: B=2, N=4096, NK=4096 — 3 launches.
//   sf:     2 k/thread, 64 atom-chunks, unconditional partial writes (fastest
//           measured shape, ~13us). S_part[z][b][k].
//   reduce: fold 64 partials + expfac -> g_t1=(kc, e*Sre) float4, g_sim float.
//   recip:  2 atoms/thread, 4 independent 1-deep accumulator chains (sf's
//           dependency shape); fused finalize resets state for graph replay.
// ---------------------------------------------------------------------------

#define NCH_SF 64
#define MAXK   8192
#define MAXBN  32768

__device__ float2 g_Spart[NCH_SF * 2 * MAXK];  // [z][b][k]
__device__ float4 g_t1[2 * MAXK];              // (kc.x, kc.y, kc.z, e*Sre) [b][k]
__device__ float  g_sim[2 * MAXK];             // e*Sim [b][k]
__device__ float  g_recip[MAXBN];              // zero at entry; re-zeroed at end
__device__ int    g_cnt_rc[64];

// ---------------- kernel 1: structure factor partials -----------------------
// 2 k per thread; grid (NK/512, B, 64). kc inline. No atomics, no zeroing.
#define SF_BLK 256
__global__ void sf_kernel(const float* __restrict__ coords,
                          const float* __restrict__ q,
                          const float* __restrict__ kvec,
                          const float* __restrict__ cell_inv,
                          int N, int NK, int nchunk) {
    __shared__ float4 sh[SF_BLK];
    int b  = blockIdx.y;
    int z  = blockIdx.z;
    int kA = blockIdx.x * (SF_BLK * 2) + threadIdx.x;
    int kB = kA + SF_BLK;
    int n0 = z * nchunk;
    int n1 = min(n0 + nchunk, N);

    const float twopi = 6.283185307179586f;
    float ci[9];
    #pragma unroll
    for (int i = 0; i < 9; i++) ci[i] = __ldg(&cell_inv[i]);

    float4 kcA = make_float4(0.f, 0.f, 0.f, 0.f);
    float4 kcB = make_float4(0.f, 0.f, 0.f, 0.f);
    if (kA < NK) {
        float kx = kvec[kA * 3 + 0], ky = kvec[kA * 3 + 1], kz = kvec[kA * 3 + 2];
        kcA.x = twopi * (kx * ci[0] + ky * ci[3] + kz * ci[6]);
        kcA.y = twopi * (kx * ci[1] + ky * ci[4] + kz * ci[7]);
        kcA.z = twopi * (kx * ci[2] + ky * ci[5] + kz * ci[8]);
    }
    if (kB < NK) {
        float kx = kvec[kB * 3 + 0], ky = kvec[kB * 3 + 1], kz = kvec[kB * 3 + 2];
        kcB.x = twopi * (kx * ci[0] + ky * ci[3] + kz * ci[6]);
        kcB.y = twopi * (kx * ci[1] + ky * ci[4] + kz * ci[7]);
        kcB.z = twopi * (kx * ci[2] + ky * ci[5] + kz * ci[8]);
    }

    float sreA = 0.f, simA = 0.f, sreB = 0.f, simB = 0.f;

    for (int t = n0; t < n1; t += SF_BLK) {
        int nt = min(SF_BLK, n1 - t);
        if ((int)threadIdx.x < nt) {
            int n = t + threadIdx.x;
            const float* cp = coords + ((size_t)b * N + n) * 3;
            sh[threadIdx.x] = make_float4(cp[0], cp[1], cp[2], q[(size_t)b * N + n]);
        }
        __syncthreads();
        #pragma unroll 4
        for (int j = 0; j < nt; j++) {
            float4 a = sh[j];
            float thA = fmaf(kcA.x, a.x, fmaf(kcA.y, a.y, kcA.z * a.z));
            float thB = fmaf(kcB.x, a.x, fmaf(kcB.y, a.y, kcB.z * a.z));
            float sA, cA, sB, cB;
            __sincosf(thA, &sA, &cA);
            __sincosf(thB, &sB, &cB);
            sreA = fmaf(a.w, cA, sreA);
            simA = fmaf(a.w, sA, simA);
            sreB = fmaf(a.w, cB, sreB);
            simB = fmaf(a.w, sB, simB);
        }
        __syncthreads();
    }
    if (kA < NK) g_Spart[(z * 2 + b) * NK + kA] = make_float2(sreA, simA);
    if (kB < NK) g_Spart[(z * 2 + b) * NK + kB] = make_float2(sreB, simB);
}

// ---------------- kernel 2: reduce partials, pack recip tiles ----------------
__global__ void reduce_kernel(const float* __restrict__ kvec,
                              const float* __restrict__ cell_inv,
                              const float* __restrict__ expfac,
                              int NK, int BK) {
    int i = blockIdx.x * blockDim.x + threadIdx.x;
    if (i >= BK) return;
    int b = i / NK;
    int k = i - b * NK;

    float sre = 0.f, sim = 0.f;
    #pragma unroll
    for (int zz = 0; zz < NCH_SF; zz++) {
        float2 p = g_Spart[(zz * 2 + b) * NK + k];
        sre += p.x; sim += p.y;
    }
    const float twopi = 6.283185307179586f;
    float ci[9];
    #pragma unroll
    for (int j = 0; j < 9; j++) ci[j] = __ldg(&cell_inv[j]);
    float kx = kvec[k * 3 + 0], ky = kvec[k * 3 + 1], kz = kvec[k * 3 + 2];
    float kcx = twopi * (kx * ci[0] + ky * ci[3] + kz * ci[6]);
    float kcy = twopi * (kx * ci[1] + ky * ci[4] + kz * ci[7]);
    float kcz = twopi * (kx * ci[2] + ky * ci[5] + kz * ci[8]);
    float e = expfac[k];
    g_t1[i]  = make_float4(kcx, kcy, kcz, e * sre);
    g_sim[i] = e * sim;
}

// ---------------- kernel 3: recip + fused finalize ---------------------------
// 2 atoms per thread; grid (N/512, B, 64). 4 independent accumulator chains.
#define RC_BLK 256
__global__ void recip_kernel(const float* __restrict__ coords,
                             const float* __restrict__ q,
                             const float* __restrict__ volume,
                             const float* __restrict__ bewald,
                             float* __restrict__ out,
                             int N, int NK, int kchunk, int BN) {
    __shared__ float4 st1[RC_BLK];
    __shared__ float  ssi[RC_BLK];
    __shared__ int s_last;
    int b  = blockIdx.y;
    int nA = blockIdx.x * (RC_BLK * 2) + threadIdx.x;
    int nB = nA + RC_BLK;
    int k0 = blockIdx.z * kchunk;
    int k1 = min(k0 + kchunk, NK);

    float xA = 0.f, yA = 0.f, zA = 0.f, xB = 0.f, yB = 0.f, zB = 0.f;
    if (nA < N) {
        const float* cp = coords + ((size_t)b * N + nA) * 3;
        xA = cp[0]; yA = cp[1]; zA = cp[2];
    }
    if (nB < N) {
        const float* cp = coords + ((size_t)b * N + nB) * 3;
        xB = cp[0]; yB = cp[1]; zB = cp[2];
    }
    // 4 independent 1-deep accumulator chains (sf's dependency shape)
    float cAc = 0.f, sAc = 0.f, cBc = 0.f, sBc = 0.f;

    for (int t = k0; t < k1; t += RC_BLK) {
        int nt = min(RC_BLK, k1 - t);
        if ((int)threadIdx.x < nt) {
            int k = t + threadIdx.x;
            st1[threadIdx.x] = g_t1[b * NK + k];
            ssi[threadIdx.x] = g_sim[b * NK + k];
        }
        __syncthreads();
        #pragma unroll 4
        for (int j = 0; j < nt; j++) {
            float4 v  = st1[j];           // kc.xyz, e*Sre
            float esi = ssi[j];           // e*Sim
            float thA = fmaf(v.x, xA, fmaf(v.y, yA, v.z * zA));
            float thB = fmaf(v.x, xB, fmaf(v.y, yB, v.z * zB));
            float sA, cA, sB, cB;
            __sincosf(thA, &sA, &cA);
            __sincosf(thB, &sB, &cB);
            cAc = fmaf(v.w, cA, cAc);
            sAc = fmaf(esi, sA, sAc);
            cBc = fmaf(v.w, cB, cBc);
            sBc = fmaf(esi, sB, sBc);
        }
        __syncthreads();
    }
    if (nA < N) atomicAdd(&g_recip[b * N + nA], cAc + sAc);
    if (nB < N) atomicAdd(&g_recip[b * N + nB], cBc + sBc);

    // ---- last z-block of this atom-slice finalizes & resets ----------------
    __threadfence();
    int slice = b * gridDim.x + blockIdx.x;
    if (threadIdx.x == 0) {
        int c = atomicAdd(&g_cnt_rc[slice], 1);
        s_last = (c == (int)gridDim.z - 1) ? 1 : 0;
    }
    __syncthreads();
    if (s_last) {
        const float BOHR = 1.8897261258369282f;
        const float INV_SQRT_PI = 0.5641895835477563f;
        float scale = BOHR / (CUDART_PI_F * volume[0]);
        float selfc = 2.0f * bewald[0] * BOHR * INV_SQRT_PI;
        int base = blockIdx.x * (RC_BLK * 2);
        #pragma unroll
        for (int a = 0; a < 2; a++) {
            int n = base + a * RC_BLK + threadIdx.x;
            if (n < N) {
                int i = b * N + n;
                float r = g_recip[i];
                g_recip[i] = 0.0f;                 // reset for next replay
                float qi = q[i];
                float phi = r * scale - qi * selfc;
                out[i] = 0.5f * qi * phi;
                out[BN + i] = phi;
            }
        }
        if (threadIdx.x == 0) g_cnt_rc[slice] = 0;
    }
}

// ---------------------------------------------------------------------------
extern "C" void kernel_launch(void* const* d_in, const int* in_sizes, int n_in,
                              void* d_out, int out_size) {
    const float* coords   = (const float*)d_in[0];
    const float* q        = (const float*)d_in[1];
    const float* cell_inv = (const float*)d_in[2];
    const float* kvec     = (const float*)d_in[3];
    const float* expfac   = (const float*)d_in[4];
    const float* volume   = (const float*)d_in[5];
    const float* bewald   = (const float*)d_in[6];
    float* out = (float*)d_out;

    int BN = in_sizes[1];       // B*N
    int NK = in_sizes[4];
    int B  = 2;                 // fixed shape for this problem
    int N  = BN / B;
    int BK = B * NK;

    // sf: 512 k / block, 64 atom-chunks -> 8*2*64 = 1024 blocks
    {
        int nchunk = (N + NCH_SF - 1) / NCH_SF;
        dim3 grid((NK + SF_BLK * 2 - 1) / (SF_BLK * 2), B, NCH_SF);
        sf_kernel<<<grid, SF_BLK>>>(coords, q, kvec, cell_inv, N, NK, nchunk);
    }

    // reduce: fold partials + expfac, pack tiles
    reduce_kernel<<<(BK + 255) / 256, 256>>>(kvec, cell_inv, expfac, NK, BK);

    // recip: 512 atoms / block, 64 k-chunks -> 8*2*64 = 1024 blocks
    {
        int kchunks = 64;
        int kchunk = (NK + kchunks - 1) / kchunks;
        dim3 grid((N + RC_BLK * 2 - 1) / (RC_BLK * 2), B, kchunks);
        recip_kernel<<<grid, RC_BLK>>>(coords, q, volume, bewald, out,
                                       N, NK, kchunk, BN);
    }
}